// round 4
// baseline (speedup 1.0000x reference)
#include <cuda_runtime.h>
#include <math.h>

#define NMAX 50000
#define EMAX 800000
#define DDIM 64

// scratch
__device__ float g_h[(size_t)NMAX * DDIM];     // transformed features
__device__ int   g_cnt[NMAX];                  // per-node degree
__device__ int   g_off[NMAX];                  // CSR offsets (exclusive scan)
__device__ int   g_fill[NMAX];                 // running fill cursor
__device__ uint2 g_edges[EMAX];                // (src, w-bits) grouped by dst

// ---------------------------------------------------------------------------
// Kernel 1: h = X @ W^T  (128 rows x 64 cols per block, 8x4 reg tile/thread)
// ---------------------------------------------------------------------------
#define XSTR 132   // smem stride for transposed X tile (mult of 4 for float4)
#define WSTR 68

__global__ void __launch_bounds__(256) gemm_kernel(
    const float* __restrict__ X, const float* __restrict__ W, int n)
{
    __shared__ float sW[DDIM * WSTR];   // sW[d*WSTR + o]
    __shared__ float sX[DDIM * XSTR];   // sX[d*XSTR + r]

    const int tid  = threadIdx.x;
    const int row0 = blockIdx.x * 128;

    #pragma unroll
    for (int i = 0; i < 16; i++) {
        int idx = tid + i * 256;
        int o = idx >> 6, d = idx & 63;
        sW[d * WSTR + o] = W[idx];
    }
    #pragma unroll
    for (int i = 0; i < 32; i++) {
        int idx = tid + i * 256;           // 8192 elems
        int r = idx >> 6, d = idx & 63;
        int gr = row0 + r;
        sX[d * XSTR + r] = (gr < n) ? X[(size_t)gr * DDIM + d] : 0.0f;
    }
    __syncthreads();

    const int tx = tid & 15;        // col group: o0 = 4*tx
    const int ty = tid >> 4;        // row group: r0 = 8*ty
    const int o0 = tx * 4;
    const int r0 = ty * 8;

    float acc[8][4];
    #pragma unroll
    for (int i = 0; i < 8; i++)
        #pragma unroll
        for (int j = 0; j < 4; j++) acc[i][j] = 0.0f;

    #pragma unroll 16
    for (int d = 0; d < DDIM; d++) {
        float4 xa = *reinterpret_cast<const float4*>(&sX[d * XSTR + r0]);
        float4 xb = *reinterpret_cast<const float4*>(&sX[d * XSTR + r0 + 4]);
        float4 wv = *reinterpret_cast<const float4*>(&sW[d * WSTR + o0]);
        float x[8] = {xa.x, xa.y, xa.z, xa.w, xb.x, xb.y, xb.z, xb.w};
        float w[4] = {wv.x, wv.y, wv.z, wv.w};
        #pragma unroll
        for (int i = 0; i < 8; i++)
            #pragma unroll
            for (int j = 0; j < 4; j++)
                acc[i][j] = fmaf(x[i], w[j], acc[i][j]);
    }

    #pragma unroll
    for (int i = 0; i < 8; i++) {
        int gr = row0 + r0 + i;
        if (gr < n) {
            float4 hv = make_float4(acc[i][0], acc[i][1], acc[i][2], acc[i][3]);
            *reinterpret_cast<float4*>(&g_h[(size_t)gr * DDIM + o0]) = hv;
        }
    }
}

// ---------------------------------------------------------------------------
// CSR build: zero counts -> histogram -> scan -> fill
// ---------------------------------------------------------------------------
__global__ void zero_kernel(int n)
{
    int i = blockIdx.x * blockDim.x + threadIdx.x;
    if (i < n) g_cnt[i] = 0;
}

__global__ void hist_kernel(const int* __restrict__ dst, int E)
{
    int i = blockIdx.x * blockDim.x + threadIdx.x;
    if (i < E) atomicAdd(&g_cnt[dst[i]], 1);   // ~16 per address, low contention
}

#define SCAN_T 1024
#define VPT 49   // 1024*49 = 50176 >= 50000

__global__ void __launch_bounds__(SCAN_T) scan_kernel(int n)
{
    __shared__ int ssum[SCAN_T];
    const int t = threadIdx.x;
    const int base = t * VPT;

    int s = 0;
    for (int k = 0; k < VPT; k++) {
        int i = base + k;
        if (i < n) s += g_cnt[i];
    }
    ssum[t] = s;
    __syncthreads();

    // Hillis-Steele inclusive scan
    for (int off = 1; off < SCAN_T; off <<= 1) {
        int v = (t >= off) ? ssum[t - off] : 0;
        __syncthreads();
        ssum[t] += v;
        __syncthreads();
    }

    int run = ssum[t] - s;   // exclusive prefix
    for (int k = 0; k < VPT; k++) {
        int i = base + k;
        if (i < n) {
            g_off[i]  = run;
            g_fill[i] = run;
            run += g_cnt[i];
        }
    }
}

__global__ void fill_kernel(const int* __restrict__ src,
                            const int* __restrict__ dst,
                            const float* __restrict__ ew, int E)
{
    int i = blockIdx.x * blockDim.x + threadIdx.x;
    if (i < E) {
        int d = dst[i];
        int slot = atomicAdd(&g_fill[d], 1);
        g_edges[slot] = make_uint2((unsigned)src[i], __float_as_uint(ew[i]));
    }
}

// ---------------------------------------------------------------------------
// Kernel D: per-node gather + skip + bias + SELU, fused.
// One warp per node; lane owns 2 columns (float2).
// ---------------------------------------------------------------------------
__global__ void __launch_bounds__(512) gather_kernel(
    const float* __restrict__ bias,
    const float* __restrict__ skipw,
    float* __restrict__ out, int n)
{
    const int lane = threadIdx.x & 31;
    const int node = blockIdx.x * 16 + (threadIdx.x >> 5);
    if (node >= n) return;

    const int col   = lane * 2;
    const int start = g_off[node];
    const int deg   = g_cnt[node];
    const int end   = start + deg;

    float2 acc = make_float2(0.0f, 0.0f);

    int e = start;
    for (; e + 4 <= end; e += 4) {
        uint2 m0 = __ldg(&g_edges[e]);
        uint2 m1 = __ldg(&g_edges[e + 1]);
        uint2 m2 = __ldg(&g_edges[e + 2]);
        uint2 m3 = __ldg(&g_edges[e + 3]);
        float2 h0 = *reinterpret_cast<const float2*>(&g_h[(size_t)m0.x * DDIM + col]);
        float2 h1 = *reinterpret_cast<const float2*>(&g_h[(size_t)m1.x * DDIM + col]);
        float2 h2 = *reinterpret_cast<const float2*>(&g_h[(size_t)m2.x * DDIM + col]);
        float2 h3 = *reinterpret_cast<const float2*>(&g_h[(size_t)m3.x * DDIM + col]);
        float w0 = __uint_as_float(m0.y);
        float w1 = __uint_as_float(m1.y);
        float w2 = __uint_as_float(m2.y);
        float w3 = __uint_as_float(m3.y);
        acc.x = fmaf(w0, h0.x, acc.x); acc.y = fmaf(w0, h0.y, acc.y);
        acc.x = fmaf(w1, h1.x, acc.x); acc.y = fmaf(w1, h1.y, acc.y);
        acc.x = fmaf(w2, h2.x, acc.x); acc.y = fmaf(w2, h2.y, acc.y);
        acc.x = fmaf(w3, h3.x, acc.x); acc.y = fmaf(w3, h3.y, acc.y);
    }
    for (; e < end; e++) {
        uint2 m = __ldg(&g_edges[e]);
        float2 hv = *reinterpret_cast<const float2*>(&g_h[(size_t)m.x * DDIM + col]);
        float w = __uint_as_float(m.y);
        acc.x = fmaf(w, hv.x, acc.x);
        acc.y = fmaf(w, hv.y, acc.y);
    }

    const float2 hself = *reinterpret_cast<const float2*>(&g_h[(size_t)node * DDIM + col]);
    const float2 sw = *reinterpret_cast<const float2*>(&skipw[col]);
    const float2 bv = *reinterpret_cast<const float2*>(&bias[col]);

    float vx = fmaf(hself.x, sw.x, acc.x) + bv.x;
    float vy = fmaf(hself.y, sw.y, acc.y) + bv.y;

    const float scale = 1.0507009873554805f;
    const float alpha = 1.6732632423543772f;
    vx = vx > 0.0f ? scale * vx : scale * alpha * (expf(vx) - 1.0f);
    vy = vy > 0.0f ? scale * vy : scale * alpha * (expf(vy) - 1.0f);

    *reinterpret_cast<float2*>(&out[(size_t)node * DDIM + col]) = make_float2(vx, vy);
}

extern "C" void kernel_launch(void* const* d_in, const int* in_sizes, int n_in,
                              void* d_out, int out_size)
{
    const float* features = (const float*)d_in[0];
    const float* W        = (const float*)d_in[1];
    const float* bias     = (const float*)d_in[2];
    const float* skipw    = (const float*)d_in[3];
    const float* ew       = (const float*)d_in[4];
    const int*   esrc     = (const int*)d_in[5];
    const int*   edst     = (const int*)d_in[6];
    float* out = (float*)d_out;

    const int n = in_sizes[0] / DDIM;     // 50000
    const int E = in_sizes[4];            // 800000

    // 1. GEMM: h = X @ W^T
    gemm_kernel<<<(n + 127) / 128, 256>>>(features, W, n);

    // 2. CSR build
    zero_kernel<<<(n + 511) / 512, 512>>>(n);
    hist_kernel<<<(E + 511) / 512, 512>>>(edst, E);
    scan_kernel<<<1, SCAN_T>>>(n);
    fill_kernel<<<(E + 511) / 512, 512>>>(esrc, edst, ew, E);

    // 3. fused gather + skip + bias + SELU
    gather_kernel<<<(n + 15) / 16, 512>>>(bias, skipw, out, n);
}

// round 5
// speedup vs baseline: 2.0816x; 2.0816x over previous
#include <cuda_runtime.h>
#include <math.h>

#define NMAX 50000
#define EMAX 800000
#define DDIM 64

#define SBLK 1024                          // nodes per scan block
#define NSB ((NMAX + SBLK - 1) / SBLK)     // 49

// scratch
__device__ float g_h[(size_t)NMAX * DDIM];     // transformed features
__device__ int   g_cnt[NMAX];                  // per-node degree
__device__ int   g_off[NMAX];                  // CSR offsets (exclusive scan)
__device__ int   g_fill[NMAX];                 // running fill cursor
__device__ int   g_bsum[NSB];                  // per-block count sums
__device__ int   g_boff[NSB];                  // per-block exclusive offsets
__device__ uint2 g_edges[EMAX];                // (src, w-bits) grouped by dst

// ---------------------------------------------------------------------------
// Kernel 1: h = X @ W^T  (128 rows x 64 cols per block, 8x4 reg tile/thread)
// ---------------------------------------------------------------------------
#define XSTR 132
#define WSTR 68

__global__ void __launch_bounds__(256) gemm_kernel(
    const float* __restrict__ X, const float* __restrict__ W, int n)
{
    __shared__ float sW[DDIM * WSTR];   // sW[d*WSTR + o]
    __shared__ float sX[DDIM * XSTR];   // sX[d*XSTR + r]

    const int tid  = threadIdx.x;
    const int row0 = blockIdx.x * 128;

    #pragma unroll
    for (int i = 0; i < 16; i++) {
        int idx = tid + i * 256;
        int o = idx >> 6, d = idx & 63;
        sW[d * WSTR + o] = W[idx];
    }
    #pragma unroll
    for (int i = 0; i < 32; i++) {
        int idx = tid + i * 256;
        int r = idx >> 6, d = idx & 63;
        int gr = row0 + r;
        sX[d * XSTR + r] = (gr < n) ? X[(size_t)gr * DDIM + d] : 0.0f;
    }
    __syncthreads();

    const int tx = tid & 15;
    const int ty = tid >> 4;
    const int o0 = tx * 4;
    const int r0 = ty * 8;

    float acc[8][4];
    #pragma unroll
    for (int i = 0; i < 8; i++)
        #pragma unroll
        for (int j = 0; j < 4; j++) acc[i][j] = 0.0f;

    #pragma unroll 16
    for (int d = 0; d < DDIM; d++) {
        float4 xa = *reinterpret_cast<const float4*>(&sX[d * XSTR + r0]);
        float4 xb = *reinterpret_cast<const float4*>(&sX[d * XSTR + r0 + 4]);
        float4 wv = *reinterpret_cast<const float4*>(&sW[d * WSTR + o0]);
        float x[8] = {xa.x, xa.y, xa.z, xa.w, xb.x, xb.y, xb.z, xb.w};
        float w[4] = {wv.x, wv.y, wv.z, wv.w};
        #pragma unroll
        for (int i = 0; i < 8; i++)
            #pragma unroll
            for (int j = 0; j < 4; j++)
                acc[i][j] = fmaf(x[i], w[j], acc[i][j]);
    }

    #pragma unroll
    for (int i = 0; i < 8; i++) {
        int gr = row0 + r0 + i;
        if (gr < n) {
            float4 hv = make_float4(acc[i][0], acc[i][1], acc[i][2], acc[i][3]);
            *reinterpret_cast<float4*>(&g_h[(size_t)gr * DDIM + o0]) = hv;
        }
    }
}

// ---------------------------------------------------------------------------
// CSR build: zero -> histogram -> 3-pass parallel scan -> fill
// ---------------------------------------------------------------------------
__global__ void zero_kernel(int n)
{
    int i = blockIdx.x * blockDim.x + threadIdx.x;
    if (i < n) g_cnt[i] = 0;
}

__global__ void hist_kernel(const int* __restrict__ dst, int E)
{
    int i = blockIdx.x * blockDim.x + threadIdx.x;
    if (i < E) atomicAdd(&g_cnt[dst[i]], 1);
}

// Pass A: per-block sum of 1024 counts
__global__ void __launch_bounds__(256) scanA_kernel(int n)
{
    __shared__ int red[256];
    const int b = blockIdx.x, t = threadIdx.x;
    const int base = b * SBLK;
    int s = 0;
    #pragma unroll
    for (int k = 0; k < 4; k++) {
        int i = base + t + k * 256;
        if (i < n) s += g_cnt[i];
    }
    red[t] = s;
    __syncthreads();
    #pragma unroll
    for (int off = 128; off > 0; off >>= 1) {
        if (t < off) red[t] += red[t + off];
        __syncthreads();
    }
    if (t == 0) g_bsum[b] = red[0];
}

// Pass B: exclusive scan of NSB partials (single small block)
__global__ void __launch_bounds__(64) scanB_kernel()
{
    __shared__ int sv[64];
    const int t = threadIdx.x;
    int v = (t < NSB) ? g_bsum[t] : 0;
    sv[t] = v;
    __syncthreads();
    #pragma unroll
    for (int off = 1; off < 64; off <<= 1) {
        int u = (t >= off) ? sv[t - off] : 0;
        __syncthreads();
        sv[t] += u;
        __syncthreads();
    }
    if (t < NSB) g_boff[t] = sv[t] - v;   // exclusive
}

// Pass C: block-local scan + global base -> g_off / g_fill
__global__ void __launch_bounds__(256) scanC_kernel(int n)
{
    __shared__ int sv[256];
    const int b = blockIdx.x, t = threadIdx.x;
    const int base = b * SBLK + t * 4;

    int c[4];
    int s = 0;
    #pragma unroll
    for (int k = 0; k < 4; k++) {
        int i = base + k;
        c[k] = (i < n) ? g_cnt[i] : 0;
        s += c[k];
    }
    sv[t] = s;
    __syncthreads();
    #pragma unroll
    for (int off = 1; off < 256; off <<= 1) {
        int u = (t >= off) ? sv[t - off] : 0;
        __syncthreads();
        sv[t] += u;
        __syncthreads();
    }

    int run = g_boff[b] + sv[t] - s;   // exclusive prefix for this thread
    #pragma unroll
    for (int k = 0; k < 4; k++) {
        int i = base + k;
        if (i < n) {
            g_off[i]  = run;
            g_fill[i] = run;
            run += c[k];
        }
    }
}

__global__ void fill_kernel(const int* __restrict__ src,
                            const int* __restrict__ dst,
                            const float* __restrict__ ew, int E)
{
    int i = blockIdx.x * blockDim.x + threadIdx.x;
    if (i < E) {
        int d = dst[i];
        int slot = atomicAdd(&g_fill[d], 1);
        g_edges[slot] = make_uint2((unsigned)src[i], __float_as_uint(ew[i]));
    }
}

// ---------------------------------------------------------------------------
// Kernel D: per-node gather + skip + bias + SELU, fused.
// One warp per node; lane owns 2 columns (float2).
// ---------------------------------------------------------------------------
__global__ void __launch_bounds__(512) gather_kernel(
    const float* __restrict__ bias,
    const float* __restrict__ skipw,
    float* __restrict__ out, int n)
{
    const int lane = threadIdx.x & 31;
    const int node = blockIdx.x * 16 + (threadIdx.x >> 5);
    if (node >= n) return;

    const int col   = lane * 2;
    const int start = g_off[node];
    const int deg   = g_cnt[node];
    const int end   = start + deg;

    float2 acc = make_float2(0.0f, 0.0f);

    int e = start;
    for (; e + 4 <= end; e += 4) {
        uint2 m0 = __ldg(&g_edges[e]);
        uint2 m1 = __ldg(&g_edges[e + 1]);
        uint2 m2 = __ldg(&g_edges[e + 2]);
        uint2 m3 = __ldg(&g_edges[e + 3]);
        float2 h0 = *reinterpret_cast<const float2*>(&g_h[(size_t)m0.x * DDIM + col]);
        float2 h1 = *reinterpret_cast<const float2*>(&g_h[(size_t)m1.x * DDIM + col]);
        float2 h2 = *reinterpret_cast<const float2*>(&g_h[(size_t)m2.x * DDIM + col]);
        float2 h3 = *reinterpret_cast<const float2*>(&g_h[(size_t)m3.x * DDIM + col]);
        float w0 = __uint_as_float(m0.y);
        float w1 = __uint_as_float(m1.y);
        float w2 = __uint_as_float(m2.y);
        float w3 = __uint_as_float(m3.y);
        acc.x = fmaf(w0, h0.x, acc.x); acc.y = fmaf(w0, h0.y, acc.y);
        acc.x = fmaf(w1, h1.x, acc.x); acc.y = fmaf(w1, h1.y, acc.y);
        acc.x = fmaf(w2, h2.x, acc.x); acc.y = fmaf(w2, h2.y, acc.y);
        acc.x = fmaf(w3, h3.x, acc.x); acc.y = fmaf(w3, h3.y, acc.y);
    }
    for (; e < end; e++) {
        uint2 m = __ldg(&g_edges[e]);
        float2 hv = *reinterpret_cast<const float2*>(&g_h[(size_t)m.x * DDIM + col]);
        float w = __uint_as_float(m.y);
        acc.x = fmaf(w, hv.x, acc.x);
        acc.y = fmaf(w, hv.y, acc.y);
    }

    const float2 hself = *reinterpret_cast<const float2*>(&g_h[(size_t)node * DDIM + col]);
    const float2 sw = *reinterpret_cast<const float2*>(&skipw[col]);
    const float2 bv = *reinterpret_cast<const float2*>(&bias[col]);

    float vx = fmaf(hself.x, sw.x, acc.x) + bv.x;
    float vy = fmaf(hself.y, sw.y, acc.y) + bv.y;

    const float scale = 1.0507009873554805f;
    const float alpha = 1.6732632423543772f;
    vx = vx > 0.0f ? scale * vx : scale * alpha * (expf(vx) - 1.0f);
    vy = vy > 0.0f ? scale * vy : scale * alpha * (expf(vy) - 1.0f);

    *reinterpret_cast<float2*>(&out[(size_t)node * DDIM + col]) = make_float2(vx, vy);
}

extern "C" void kernel_launch(void* const* d_in, const int* in_sizes, int n_in,
                              void* d_out, int out_size)
{
    const float* features = (const float*)d_in[0];
    const float* W        = (const float*)d_in[1];
    const float* bias     = (const float*)d_in[2];
    const float* skipw    = (const float*)d_in[3];
    const float* ew       = (const float*)d_in[4];
    const int*   esrc     = (const int*)d_in[5];
    const int*   edst     = (const int*)d_in[6];
    float* out = (float*)d_out;

    const int n = in_sizes[0] / DDIM;     // 50000
    const int E = in_sizes[4];            // 800000

    // 1. GEMM: h = X @ W^T
    gemm_kernel<<<(n + 127) / 128, 256>>>(features, W, n);

    // 2. CSR build
    zero_kernel<<<(n + 511) / 512, 512>>>(n);
    hist_kernel<<<(E + 511) / 512, 512>>>(edst, E);
    scanA_kernel<<<NSB, 256>>>(n);
    scanB_kernel<<<1, 64>>>();
    scanC_kernel<<<NSB, 256>>>(n);
    fill_kernel<<<(E + 511) / 512, 512>>>(esrc, edst, ew, E);

    // 3. fused gather + skip + bias + SELU
    gather_kernel<<<(n + 15) / 16, 512>>>(bias, skipw, out, n);
}